// round 2
// baseline (speedup 1.0000x reference)
#include <cuda_runtime.h>
#include <cstdint>

// Packed f32x2 FMA — only reachable via PTX (ptxas never auto-fuses 2x fmaf).
#define FMA2(d, a, b, c) \
    asm("fma.rn.f32x2 %0, %1, %2, %3;" : "=l"(d) : "l"(a), "l"(b), "l"(c))

__device__ __forceinline__ unsigned long long pack2(float lo, float hi) {
    unsigned long long r;
    asm("mov.b64 %0, {%1, %2};" : "=l"(r) : "f"(lo), "f"(hi));
    return r;
}

namespace {
constexpr int H  = 224;
constexpr int W  = 224;
constexpr int HO = 222;
constexpr int WO = 222;
constexpr int OC = 64;
constexpr int BY = 8;     // output rows per block
constexpr int QX = 56;    // x-quads per row (each quad = 4 outputs, last partly masked)
constexpr int TPB = 4 * QX;  // 224 threads: 4 row-pairs x 56 quads
}

// Each thread: 2 output rows x 4 output cols (2 packed pairs) x all 64 channels.
// Per channel iteration per warp: 5 LDS.128 + 4 STG.64 for 36 FFMA2.
__global__ __launch_bounds__(TPB, 3)
void Conv2d_68298569941797_kernel(const float* __restrict__ data,
                                  const float* __restrict__ weight,
                                  float* __restrict__ out) {
    __shared__ float s_in[(BY + 2) * W];          // 10 input rows
    __shared__ unsigned long long s_w[OC * 10];   // 9 packed (w,w) + pad -> LDS.128-friendly

    const int tid = threadIdx.x;
    const int b   = blockIdx.y;
    const int y0  = blockIdx.x * BY;

    // Stage input rows y0..y0+9 (row-clamped for the y-tail tile).
    for (int i = tid; i < (BY + 2) * W; i += TPB) {
        int rr = i / W;
        int cc = i - rr * W;
        int gr = y0 + rr;
        if (gr > H - 1) gr = H - 1;
        s_in[i] = data[((size_t)b * H + gr) * W + cc];
    }
    // Stage weights, duplicated into both f32x2 lanes.
    for (int i = tid; i < OC * 9; i += TPB) {
        int o = i / 9;
        int k = i - o * 9;
        float w = weight[i];
        s_w[o * 10 + k] = pack2(w, w);
    }
    __syncthreads();

    const int ry = tid / QX;          // 0..3  -> row pair
    const int q  = tid - ry * QX;     // 0..55 -> x quad
    const int r0 = 2 * ry;            // local input-row base
    const int x0 = 4 * q;

    // Build 20 packed input operands: 4 rows x 5 sliding pairs over cols x0..x0+5.
    const int c4 = (x0 + 4 < W) ? x0 + 4 : W - 1;   // clamp for q=55 (unused outputs)
    const int c5 = (x0 + 5 < W) ? x0 + 5 : W - 1;
    unsigned long long P[4][5];
#pragma unroll
    for (int rr = 0; rr < 4; ++rr) {
        const float* rp = s_in + (r0 + rr) * W;
        float a0 = rp[x0], a1 = rp[x0 + 1], a2 = rp[x0 + 2], a3 = rp[x0 + 3];
        float a4 = rp[c4], a5 = rp[c5];
        P[rr][0] = pack2(a0, a1);
        P[rr][1] = pack2(a1, a2);
        P[rr][2] = pack2(a2, a3);
        P[rr][3] = pack2(a3, a4);
        P[rr][4] = pack2(a4, a5);
    }

    const int gr0 = y0 + r0;          // global output rows
    const int gr1 = gr0 + 1;
    const bool v0 = (gr0 < HO);
    const bool v1 = (gr1 < HO);
    const bool vx = (q != QX - 1);    // second pair (x0+2, x0+3) valid?

    const size_t plane = (size_t)HO * WO;
    float* op = out + ((size_t)(b * OC) * HO + gr0) * WO + x0;

    const ulonglong2* w2 = reinterpret_cast<const ulonglong2*>(s_w);

#pragma unroll 2
    for (int o = 0; o < OC; ++o) {
        const ulonglong2* wo = w2 + o * 5;
        ulonglong2 w01 = wo[0];
        ulonglong2 w23 = wo[1];
        ulonglong2 w45 = wo[2];
        ulonglong2 w67 = wo[3];
        ulonglong2 w8x = wo[4];   // .y is padding

        unsigned long long A00 = 0ull, A01 = 0ull, A10 = 0ull, A11 = 0ull;

        // Row gr0, pair (x0, x0+1): taps rows r0..r0+2, cols 0..2
        FMA2(A00, P[0][0], w01.x, A00); FMA2(A00, P[0][1], w01.y, A00); FMA2(A00, P[0][2], w23.x, A00);
        FMA2(A00, P[1][0], w23.y, A00); FMA2(A00, P[1][1], w45.x, A00); FMA2(A00, P[1][2], w45.y, A00);
        FMA2(A00, P[2][0], w67.x, A00); FMA2(A00, P[2][1], w67.y, A00); FMA2(A00, P[2][2], w8x.x, A00);
        // Row gr0, pair (x0+2, x0+3): cols shifted by 2
        FMA2(A01, P[0][2], w01.x, A01); FMA2(A01, P[0][3], w01.y, A01); FMA2(A01, P[0][4], w23.x, A01);
        FMA2(A01, P[1][2], w23.y, A01); FMA2(A01, P[1][3], w45.x, A01); FMA2(A01, P[1][4], w45.y, A01);
        FMA2(A01, P[2][2], w67.x, A01); FMA2(A01, P[2][3], w67.y, A01); FMA2(A01, P[2][4], w8x.x, A01);
        // Row gr1, pair (x0, x0+1): rows shifted by 1
        FMA2(A10, P[1][0], w01.x, A10); FMA2(A10, P[1][1], w01.y, A10); FMA2(A10, P[1][2], w23.x, A10);
        FMA2(A10, P[2][0], w23.y, A10); FMA2(A10, P[2][1], w45.x, A10); FMA2(A10, P[2][2], w45.y, A10);
        FMA2(A10, P[3][0], w67.x, A10); FMA2(A10, P[3][1], w67.y, A10); FMA2(A10, P[3][2], w8x.x, A10);
        // Row gr1, pair (x0+2, x0+3)
        FMA2(A11, P[1][2], w01.x, A11); FMA2(A11, P[1][3], w01.y, A11); FMA2(A11, P[1][4], w23.x, A11);
        FMA2(A11, P[2][2], w23.y, A11); FMA2(A11, P[2][3], w45.x, A11); FMA2(A11, P[2][4], w45.y, A11);
        FMA2(A11, P[3][2], w67.x, A11); FMA2(A11, P[3][3], w67.y, A11); FMA2(A11, P[3][4], w8x.x, A11);

        if (v0) {
            *reinterpret_cast<unsigned long long*>(op) = A00;
            if (vx) *reinterpret_cast<unsigned long long*>(op + 2) = A01;
        }
        if (v1) {
            *reinterpret_cast<unsigned long long*>(op + WO) = A10;
            if (vx) *reinterpret_cast<unsigned long long*>(op + WO + 2) = A11;
        }
        op += plane;
    }
}

extern "C" void kernel_launch(void* const* d_in, const int* in_sizes, int n_in,
                              void* d_out, int out_size) {
    const float* data   = (const float*)d_in[0];
    const float* weight = (const float*)d_in[1];
    float* out          = (float*)d_out;

    dim3 grid((HO + BY - 1) / BY, 32);   // (28, 32)
    Conv2d_68298569941797_kernel<<<grid, TPB>>>(data, weight, out);
}

// round 3
// speedup vs baseline: 1.7219x; 1.7219x over previous
#include <cuda_runtime.h>
#include <cstdint>

// Packed f32x2 FMA — only reachable via PTX (ptxas never auto-fuses 2x fmaf).
#define FMA2(d, a, b, c) \
    asm("fma.rn.f32x2 %0, %1, %2, %3;" : "=l"(d) : "l"(a), "l"(b), "l"(c))

__device__ __forceinline__ unsigned long long pack2(float lo, float hi) {
    unsigned long long r;
    asm("mov.b64 %0, {%1, %2};" : "=l"(r) : "f"(lo), "f"(hi));
    return r;
}

namespace {
constexpr int H  = 224;
constexpr int W  = 224;
constexpr int HO = 222;
constexpr int WO = 222;
constexpr int OC = 64;
constexpr int TPB = 224;   // 2 channel-halves x 2 rows x 56 x-slots
}

// Block: 2 output rows (even base -> fixed parity per r) x 222 cols x 64 ch x 1 batch.
// Thread: 1 row x 4 cols (one 16B-aligned quad, or the 2-col edge) x 32 channels.
// Parity-shifted quad mapping makes every 4-wide store STG.128 (16B-aligned):
//   even row: quads at x=0,4,...,216  + tail pair (220,221)
//   odd  row: quads at x=2,6,...,218  + head pair (0,1)
__global__ __launch_bounds__(TPB, 5)
void Conv2d_68298569941797_kernel(const float* __restrict__ data,
                                  const float* __restrict__ weight,
                                  float* __restrict__ out) {
    __shared__ float s_in[4 * W];                 // input rows y0..y0+3
    __shared__ unsigned long long s_w[OC * 10];   // 9 packed (w,w) + pad per ch

    const int tid = threadIdx.x;
    const int b   = blockIdx.y;
    const int y0  = blockIdx.x * 2;               // even output-row base = input-row base

    // Stage 4 input rows (always in bounds: y0<=220 -> rows <=223).
    const float* src = data + ((size_t)b * H + y0) * W;
    for (int i = tid; i < 4 * W; i += TPB) s_in[i] = src[i];

    // Stage weights, duplicated into both f32x2 lanes.
    for (int i = tid; i < OC * 9; i += TPB) {
        int o = i / 9;
        int k = i - o * 9;
        float w = weight[i];
        s_w[o * 10 + k] = pack2(w, w);
    }
    __syncthreads();

    const int h   = tid / 112;           // channel half: 0 -> ch 0..31, 1 -> ch 32..63
    const int rem = tid - h * 112;
    const int r   = rem / 56;            // 0 = even output row, 1 = odd
    const int q   = rem - r * 56;        // 0..55 x-slot

    bool quad;
    int  x0;
    if (r == 0) { quad = (q < 55); x0 = quad ? 4 * q : 220; }   // even row
    else        { quad = (q >= 1); x0 = quad ? 4 * q - 2 : 0; } // odd row

    // Build 15 packed input operands: 3 input rows (r..r+2) x 5 sliding pairs.
    // Cols x0..x0+5; clamp +4/+5 only matters for the even-row tail (unused outputs).
    const int c4 = (x0 + 4 < W) ? x0 + 4 : W - 1;
    const int c5 = (x0 + 5 < W) ? x0 + 5 : W - 1;
    unsigned long long P[3][5];
#pragma unroll
    for (int rr = 0; rr < 3; ++rr) {
        const float* rp = s_in + (r + rr) * W;
        float a0 = rp[x0], a1 = rp[x0 + 1], a2 = rp[x0 + 2], a3 = rp[x0 + 3];
        float a4 = rp[c4], a5 = rp[c5];
        P[rr][0] = pack2(a0, a1);
        P[rr][1] = pack2(a1, a2);
        P[rr][2] = pack2(a2, a3);
        P[rr][3] = pack2(a3, a4);
        P[rr][4] = pack2(a4, a5);
    }

    const size_t plane = (size_t)HO * WO;
    float* op = out + (((size_t)b * OC + h * 32) * HO + (y0 + r)) * WO + x0;
    const ulonglong2* w2 = reinterpret_cast<const ulonglong2*>(s_w) + (size_t)h * 32 * 5;

#pragma unroll 2
    for (int o = 0; o < 32; ++o) {
        const ulonglong2* wo = w2 + o * 5;
        ulonglong2 w01 = wo[0];
        ulonglong2 w23 = wo[1];
        ulonglong2 w45 = wo[2];
        ulonglong2 w67 = wo[3];
        ulonglong2 w8x = wo[4];   // .y is padding

        unsigned long long A0 = 0ull, A1 = 0ull;

        // Outputs (x0, x0+1): sliding pairs 0..2
        FMA2(A0, P[0][0], w01.x, A0); FMA2(A0, P[0][1], w01.y, A0); FMA2(A0, P[0][2], w23.x, A0);
        FMA2(A0, P[1][0], w23.y, A0); FMA2(A0, P[1][1], w45.x, A0); FMA2(A0, P[1][2], w45.y, A0);
        FMA2(A0, P[2][0], w67.x, A0); FMA2(A0, P[2][1], w67.y, A0); FMA2(A0, P[2][2], w8x.x, A0);
        // Outputs (x0+2, x0+3): sliding pairs 2..4
        FMA2(A1, P[0][2], w01.x, A1); FMA2(A1, P[0][3], w01.y, A1); FMA2(A1, P[0][4], w23.x, A1);
        FMA2(A1, P[1][2], w23.y, A1); FMA2(A1, P[1][3], w45.x, A1); FMA2(A1, P[1][4], w45.y, A1);
        FMA2(A1, P[2][2], w67.x, A1); FMA2(A1, P[2][3], w67.y, A1); FMA2(A1, P[2][4], w8x.x, A1);

        if (quad) {
            ulonglong2 v; v.x = A0; v.y = A1;
            *reinterpret_cast<ulonglong2*>(op) = v;           // STG.128, 16B-aligned
        } else {
            *reinterpret_cast<unsigned long long*>(op) = A0;  // edge pair, STG.64
        }
        op += plane;
    }
}

extern "C" void kernel_launch(void* const* d_in, const int* in_sizes, int n_in,
                              void* d_out, int out_size) {
    const float* data   = (const float*)d_in[0];
    const float* weight = (const float*)d_in[1];
    float* out          = (float*)d_out;

    dim3 grid(HO / 2, 32);   // (111, 32)
    Conv2d_68298569941797_kernel<<<grid, TPB>>>(data, weight, out);
}